// round 6
// baseline (speedup 1.0000x reference)
#include <cuda_runtime.h>

#define BLOCK 256
#define EPB   64        // elements per block (4 threads per element)
#define TSEQ  200

typedef unsigned long long u64;

// ---- tanh.approx-based activations (MUFU.TANH: ~1.4e-5 abs err) ----
__device__ __forceinline__ float tanha_(float x) {
    float y; asm("tanh.approx.f32 %0, %1;" : "=f"(y) : "f"(x)); return y;
}
__device__ __forceinline__ float sigm_(float x) {
    return fmaf(tanha_(0.5f * x), 0.5f, 0.5f);
}

// ---- packed f32x2 ops ----
__device__ __forceinline__ u64 fma2(u64 a, u64 b, u64 c) {
    u64 d; asm("fma.rn.f32x2 %0, %1, %2, %3;" : "=l"(d) : "l"(a), "l"(b), "l"(c));
    return d;
}
__device__ __forceinline__ u64 add2(u64 a, u64 b) {
    u64 d; asm("add.rn.f32x2 %0, %1, %2;" : "=l"(d) : "l"(a), "l"(b));
    return d;
}
__device__ __forceinline__ u64 pack2(float lo, float hi) {
    u64 r; asm("mov.b64 %0, {%1, %2};" : "=l"(r) : "f"(lo), "f"(hi)); return r;
}
__device__ __forceinline__ void unpack2(float& lo, float& hi, u64 v) {
    asm("mov.b64 {%0, %1}, %2;" : "=f"(lo), "=f"(hi) : "l"(v));
}

// smem: Wout packs. [800 phys-col][4 r][4 qpack] u64 = 12800 u64 = 100 KB.
// phys col (4t+s) for r-class r holds logical column 4t + (s^r) (slot s = unit r^s).
#define SM_U64 12800

// one LSTM unit step, tree-split gate accumulation (2x4 chains + add2)
__device__ __forceinline__ float unit_step(
    const u64* __restrict__ inp,   // 8 broadcast packs
    const u64* __restrict__ wIF, const u64* __restrict__ wGO,
    u64 bIF, u64 bGO, float& c)
{
    u64 gIFa = bIF, gGOa = bGO;
    u64 gIFb = fma2(inp[4], wIF[4], 0ull);
    u64 gGOb = fma2(inp[4], wGO[4], 0ull);
    #pragma unroll
    for (int in = 0; in < 4; in++) {
        gIFa = fma2(inp[in], wIF[in], gIFa);
        gGOa = fma2(inp[in], wGO[in], gGOa);
    }
    #pragma unroll
    for (int in = 5; in < 8; in++) {
        gIFb = fma2(inp[in], wIF[in], gIFb);
        gGOb = fma2(inp[in], wGO[in], gGOb);
    }
    u64 gIF = add2(gIFa, gIFb);
    u64 gGO = add2(gGOa, gGOb);
    float iv, fv, gv, ov;
    unpack2(iv, fv, gIF);
    unpack2(gv, ov, gGO);
    float i = sigm_(iv), f = sigm_(fv), g = tanha_(gv), o = sigm_(ov);
    c = f * c + i * g;
    return o * tanha_(c);
}

__global__ void __launch_bounds__(BLOCK, 2) lstm_fused_kernel(
    const float* __restrict__ x,
    const float* __restrict__ Wih0, const float* __restrict__ Whh0,
    const float* __restrict__ bih0, const float* __restrict__ bhh0,
    const float* __restrict__ Wih1, const float* __restrict__ Whh1,
    const float* __restrict__ bih1, const float* __restrict__ bhh1,
    const float* __restrict__ Wout, const float* __restrict__ bout,
    float* __restrict__ out)
{
    extern __shared__ u64 smu[];
    const int tid  = threadIdx.x;
    const int r    = tid & 3;                     // unit index / output quarter
    const int elem = blockIdx.x * EPB + (tid >> 2);

    // ---- stage Wout packs with per-r column permutation ----
    for (int idx = tid; idx < SM_U64; idx += BLOCK) {
        int c  = idx >> 4;
        int r4 = (idx >> 2) & 3;
        int q  = idx & 3;
        int srcc = (c & ~3) | ((c & 3) ^ r4);     // logical column for this r-class
        int row0 = 7 * r4 + 2 * q;                // rows 7r .. 7r+6 (q=3 hi is dummy)
        float lo = Wout[row0 * 800 + srcc];
        float hi = (q < 3) ? Wout[(row0 + 1) * 800 + srcc] : 0.0f;
        smu[idx] = pack2(lo, hi);
    }
    __syncthreads();

    // ---- gate weights -> registers (slot s of h-inputs carries unit r^s) ----
    u64 wIF0[8], wGO0[8], wIF1[8], wGO1[8];
    #pragma unroll
    for (int in = 0; in < 4; in++) {
        int cs = r ^ in;                           // permuted column for h slots
        wIF0[in]     = pack2(Wih0[(0  + r) * 4 + in], Wih0[(4  + r) * 4 + in]);
        wGO0[in]     = pack2(Wih0[(8  + r) * 4 + in], Wih0[(12 + r) * 4 + in]);
        wIF0[4 + in] = pack2(Whh0[(0  + r) * 4 + cs], Whh0[(4  + r) * 4 + cs]);
        wGO0[4 + in] = pack2(Whh0[(8  + r) * 4 + cs], Whh0[(12 + r) * 4 + cs]);
        wIF1[in]     = pack2(Wih1[(0  + r) * 4 + cs], Wih1[(4  + r) * 4 + cs]);
        wGO1[in]     = pack2(Wih1[(8  + r) * 4 + cs], Wih1[(12 + r) * 4 + cs]);
        wIF1[4 + in] = pack2(Whh1[(0  + r) * 4 + cs], Whh1[(4  + r) * 4 + cs]);
        wGO1[4 + in] = pack2(Whh1[(8  + r) * 4 + cs], Whh1[(12 + r) * 4 + cs]);
    }
    const u64 bIF0 = pack2(bih0[r] + bhh0[r],           bih0[4 + r]  + bhh0[4 + r]);
    const u64 bGO0 = pack2(bih0[8 + r] + bhh0[8 + r],   bih0[12 + r] + bhh0[12 + r]);
    const u64 bIF1 = pack2(bih1[r] + bhh1[r],           bih1[4 + r]  + bhh1[4 + r]);
    const u64 bGO1 = pack2(bih1[8 + r] + bhh1[8 + r],   bih1[12 + r] + bhh1[12 + r]);

    u64 acc[4];
    #pragma unroll
    for (int q = 0; q < 4; q++)
        acc[q] = pack2(bout[7 * r + 2 * q], (q < 3) ? bout[7 * r + 2 * q + 1] : 0.0f);

    const float4* xp = (const float4*)(x + (size_t)elem * (TSEQ * 4));
    const ulonglong2* wop = (const ulonglong2*)smu + (size_t)r * 2;

    float h1s[4] = {0.f, 0.f, 0.f, 0.f};          // slot s = unit r^s
    float h2s[4] = {0.f, 0.f, 0.f, 0.f};
    float c1 = 0.f, c2 = 0.f;

    // ---- prologue: h1(0) from x[0], h1_init = 0 ----
    {
        const float4 x0 = xp[0];
        u64 inp[8];
        inp[0] = pack2(x0.x, x0.x); inp[1] = pack2(x0.y, x0.y);
        inp[2] = pack2(x0.z, x0.z); inp[3] = pack2(x0.w, x0.w);
        inp[4] = 0; inp[5] = 0; inp[6] = 0; inp[7] = 0;
        float h1 = unit_step(inp, wIF0, wGO0, bIF0, bGO0, c1);
        float a1 = __shfl_xor_sync(0xffffffffu, h1, 1);
        float a2 = __shfl_xor_sync(0xffffffffu, h1, 2);
        float a3 = __shfl_xor_sync(0xffffffffu, h1, 3);
        h1s[0] = h1; h1s[1] = a1; h1s[2] = a2; h1s[3] = a3;
    }

    // ---- pipelined main loop: iteration t computes L2(t) || L1(t+1) ----
    #pragma unroll 1
    for (int tg = 0; tg < TSEQ; tg += 4) {
        // preload x[tg+1 .. tg+4] (MLP=4); clamp OOB tail (result discarded)
        float4 xg[4];
        #pragma unroll
        for (int u = 0; u < 4; u++) {
            int ix = tg + 1 + u;
            if (ix > TSEQ - 1) ix = TSEQ - 1;
            xg[u] = xp[ix];
        }

        #pragma unroll
        for (int u = 0; u < 4; u++) {
            const int t = tg + u;

            // inputs for L2(t): h1(t), h2(t-1)
            u64 inp2[8];
            inp2[0] = pack2(h1s[0], h1s[0]); inp2[1] = pack2(h1s[1], h1s[1]);
            inp2[2] = pack2(h1s[2], h1s[2]); inp2[3] = pack2(h1s[3], h1s[3]);
            inp2[4] = pack2(h2s[0], h2s[0]); inp2[5] = pack2(h2s[1], h2s[1]);
            inp2[6] = pack2(h2s[2], h2s[2]); inp2[7] = pack2(h2s[3], h2s[3]);

            // inputs for L1(t+1): x[t+1], h1(t)  — independent of L2(t)
            const float4 xt = xg[u];
            u64 inp1[8];
            inp1[0] = pack2(xt.x, xt.x); inp1[1] = pack2(xt.y, xt.y);
            inp1[2] = pack2(xt.z, xt.z); inp1[3] = pack2(xt.w, xt.w);
            inp1[4] = inp2[0]; inp1[5] = inp2[1];
            inp1[6] = inp2[2]; inp1[7] = inp2[3];

            // two independent unit steps — chains interleave
            float h2 = unit_step(inp2, wIF1, wGO1, bIF1, bGO1, c2);
            float h1 = unit_step(inp1, wIF0, wGO0, bIF0, bGO0, c1);

            // parallel butterflies (independent)
            {
                float a1 = __shfl_xor_sync(0xffffffffu, h2, 1);
                float a2 = __shfl_xor_sync(0xffffffffu, h2, 2);
                float a3 = __shfl_xor_sync(0xffffffffu, h2, 3);
                h2s[0] = h2; h2s[1] = a1; h2s[2] = a2; h2s[3] = a3;
            }
            {
                float a1 = __shfl_xor_sync(0xffffffffu, h1, 1);
                float a2 = __shfl_xor_sync(0xffffffffu, h1, 2);
                float a3 = __shfl_xor_sync(0xffffffffu, h1, 3);
                h1s[0] = h1; h1s[1] = a1; h1s[2] = a2; h1s[3] = a3;
            }

            // GEMV for step t (off the recurrence critical path)
            #pragma unroll
            for (int s = 0; s < 4; s++) {
                u64 hp = pack2(h2s[s], h2s[s]);
                const ulonglong2* wrow = wop + (size_t)(4 * t + s) * 8;
                ulonglong2 w0 = wrow[0];
                ulonglong2 w1 = wrow[1];
                acc[0] = fma2(hp, w0.x, acc[0]);
                acc[1] = fma2(hp, w0.y, acc[1]);
                acc[2] = fma2(hp, w1.x, acc[2]);
                acc[3] = fma2(hp, w1.y, acc[3]);
            }
        }
    }

    // ---- write 7 outputs ----
    float* op = out + (size_t)elem * 28 + 7 * r;
    float o0, o1, o2, o3, o4, o5, o6, dummy;
    unpack2(o0, o1, acc[0]); unpack2(o2, o3, acc[1]);
    unpack2(o4, o5, acc[2]); unpack2(o6, dummy, acc[3]);
    op[0] = o0; op[1] = o1; op[2] = o2; op[3] = o3;
    op[4] = o4; op[5] = o5; op[6] = o6;
}

extern "C" void kernel_launch(void* const* d_in, const int* in_sizes, int n_in,
                              void* d_out, int out_size)
{
    const float* x    = (const float*)d_in[0];
    const float* Wih0 = (const float*)d_in[1];
    const float* Whh0 = (const float*)d_in[2];
    const float* bih0 = (const float*)d_in[3];
    const float* bhh0 = (const float*)d_in[4];
    const float* Wih1 = (const float*)d_in[5];
    const float* Whh1 = (const float*)d_in[6];
    const float* bih1 = (const float*)d_in[7];
    const float* bhh1 = (const float*)d_in[8];
    const float* Wout = (const float*)d_in[9];
    const float* bout = (const float*)d_in[10];
    float* out = (float*)d_out;

    const int B = in_sizes[0] / (TSEQ * 4);          // 32768
    const int smem_bytes = SM_U64 * sizeof(u64);     // 102400 B

    cudaFuncSetAttribute(lstm_fused_kernel,
                         cudaFuncAttributeMaxDynamicSharedMemorySize, smem_bytes);

    lstm_fused_kernel<<<B / EPB, BLOCK, smem_bytes>>>(
        x, Wih0, Whh0, bih0, bhh0, Wih1, Whh1, bih1, bhh1, Wout, bout, out);
}